// round 7
// baseline (speedup 1.0000x reference)
#include <cuda_runtime.h>
#include <cuda_fp16.h>

#define BATCH   256
#define IN_DIM  1024
#define WIDTH   64000
#define KOUT    10
#define GROUP   (WIDTH / KOUT)   // 6400
#define NS      80               // splits per group for fused layer3+reduce
#define JS      (GROUP / NS)     // 80 neurons per block
#define L3WARPS 8
#define JW      (JS / L3WARPS)   // 10 neurons per warp

// Scratch — fp16 activations, [neuron][batch] layout, 16B-aligned
__device__ __align__(256) __half g_xT[IN_DIM * BATCH];     // 0.5 MB
__device__ __align__(256) __half g_bufA[WIDTH * BATCH];    // 32.8 MB
__device__ __align__(256) __half g_bufB[WIDTH * BATCH];    // 32.8 MB
__device__ float4 g_coef[3 * WIDTH];                       // 3 MB
__device__ float  g_part[KOUT * NS * BATCH];               // 800 KB

// ---------------------------------------------------------------------------
// L2 evict_last policy helpers (keep activation buffers L2-resident)
__device__ __forceinline__ unsigned long long mk_policy() {
    unsigned long long p;
    asm("createpolicy.fractional.L2::evict_last.b64 %0, 0.875;" : "=l"(p));
    return p;
}
__device__ __forceinline__ uint4 ldg_el(const uint4* a, unsigned long long pol) {
    uint4 r;
    asm volatile("ld.global.L2::cache_hint.v4.u32 {%0,%1,%2,%3}, [%4], %5;"
                 : "=r"(r.x), "=r"(r.y), "=r"(r.z), "=r"(r.w)
                 : "l"(a), "l"(pol));
    return r;
}
__device__ __forceinline__ void stg_el(uint4* a, uint4 v, unsigned long long pol) {
    asm volatile("st.global.L2::cache_hint.v4.u32 [%0], {%1,%2,%3,%4}, %5;"
                 :: "l"(a), "r"(v.x), "r"(v.y), "r"(v.z), "r"(v.w), "l"(pol)
                 : "memory");
}

// ---------------------------------------------------------------------------
// Fused prologue: blocks [0,256) transpose x -> xT fp16; blocks [256, 256+750)
// compute per-neuron coefficients softmax(w) @ GATE_COEF.
__global__ __launch_bounds__(256)
void k_pre(const float* __restrict__ x,
           const float* __restrict__ w1,
           const float* __restrict__ w2,
           const float* __restrict__ w3) {
    if (blockIdx.x < 256) {
        // transpose tile: 32 dims x 32 batch, 256 threads = (32, 8)
        __shared__ float tile[32][33];
        int d0 = (blockIdx.x & 31) * 32;
        int b0 = (blockIdx.x >> 5) * 32;
        int tx = threadIdx.x & 31;
        int ty = threadIdx.x >> 5;       // 0..7
        #pragma unroll
        for (int r = 0; r < 4; r++)      // batch rows
            tile[ty + r * 8][tx] =
                x[(size_t)(b0 + ty + r * 8) * IN_DIM + d0 + tx];
        __syncthreads();
        #pragma unroll
        for (int r = 0; r < 4; r++)      // dim rows
            g_xT[(size_t)(d0 + ty + r * 8) * BATCH + b0 + tx] =
                __float2half_rn(tile[tx][ty + r * 8]);
        return;
    }

    int tid = (blockIdx.x - 256) * blockDim.x + threadIdx.x;
    if (tid >= 3 * WIDTH) return;
    int layer = tid / WIDTH;
    int n     = tid - layer * WIDTH;
    const float* w = (layer == 0) ? w1 : (layer == 1) ? w2 : w3;
    w += (size_t)n * 16;

    float v[16];
    float m = -1e30f;
    #pragma unroll
    for (int i = 0; i < 16; i++) { v[i] = w[i]; m = fmaxf(m, v[i]); }
    float s = 0.f;
    #pragma unroll
    for (int i = 0; i < 16; i++) { v[i] = __expf(v[i] - m); s += v[i]; }
    float inv = 1.0f / s;
    #pragma unroll
    for (int i = 0; i < 16; i++) v[i] *= inv;

    float c0 = v[8]+v[9]+v[10]+v[11]+v[12]+v[13]+v[14]+v[15];
    float c1 = v[2]+v[3]+v[6]+v[7] - v[8]-v[9]-v[12]-v[13];
    float c2 = v[4]+v[5]+v[6]+v[7] - v[8]-v[9]-v[10]-v[11];
    float c3 = v[1] - v[2] - v[4] - 2.f*v[6] - v[7]
             + v[8] + 2.f*v[9] + v[11] + v[13] - v[14];
    g_coef[tid] = make_float4(c0, c1, c2, c3);
}

// ---------------------------------------------------------------------------
__device__ __forceinline__ __half2 gate_h2(float4 c, __half2 ah, __half2 bh) {
    float2 a = __half22float2(ah);
    float2 b = __half22float2(bh);
    float rx = fmaf(c.w * a.x, b.x, fmaf(c.y, a.x, fmaf(c.z, b.x, c.x)));
    float ry = fmaf(c.w * a.y, b.y, fmaf(c.y, a.y, fmaf(c.z, b.y, c.x)));
    return __floats2half2_rn(rx, ry);
}

__device__ __forceinline__ uint4 gate_u4(float4 c, uint4 av, uint4 bv) {
    uint4 r;
    ((__half2*)&r)[0] = gate_h2(c, ((__half2*)&av)[0], ((__half2*)&bv)[0]);
    ((__half2*)&r)[1] = gate_h2(c, ((__half2*)&av)[1], ((__half2*)&bv)[1]);
    ((__half2*)&r)[2] = gate_h2(c, ((__half2*)&av)[2], ((__half2*)&bv)[2]);
    ((__half2*)&r)[3] = gate_h2(c, ((__half2*)&av)[3], ((__half2*)&bv)[3]);
    return r;
}

// One logic layer, fp16 in/out, TWO neurons per warp, L2 evict_last on
// all activation traffic. srcSel: 0=xT, 1=bufA, 2=bufB ; dstSel: 1 or 2.
__global__ __launch_bounds__(256)
void k_layer(int srcSel, int dstSel, int coefOff,
             const int* __restrict__ ia, const int* __restrict__ ib) {
    int warp = blockIdx.x * 8 + threadIdx.y;
    int n0   = warp * 2;
    int n1   = n0 + 1;
    int lane = threadIdx.x;

    const __half* src = (srcSel == 0) ? g_xT : (srcSel == 1) ? g_bufA : g_bufB;
    __half*       dst = (dstSel == 1) ? g_bufA : g_bufB;
    unsigned long long pol = mk_policy();

    int A0 = __ldg(ia + n0), B0 = __ldg(ib + n0);
    int A1 = __ldg(ia + n1), B1 = __ldg(ib + n1);
    float4 c0 = __ldg(&g_coef[coefOff + n0]);
    float4 c1 = __ldg(&g_coef[coefOff + n1]);

    // 4 independent 16B gathers in flight per lane, L2-resident
    uint4 a0 = ldg_el((const uint4*)(src + (size_t)A0 * BATCH) + lane, pol);
    uint4 b0 = ldg_el((const uint4*)(src + (size_t)B0 * BATCH) + lane, pol);
    uint4 a1 = ldg_el((const uint4*)(src + (size_t)A1 * BATCH) + lane, pol);
    uint4 b1 = ldg_el((const uint4*)(src + (size_t)B1 * BATCH) + lane, pol);

    stg_el((uint4*)(dst + (size_t)n0 * BATCH) + lane, gate_u4(c0, a0, b0), pol);
    stg_el((uint4*)(dst + (size_t)n1 * BATCH) + lane, gate_u4(c1, a1, b1), pol);
}

// ---------------------------------------------------------------------------
// Fused layer-3 + partial group sum. 8 warps/block, warp-per-neuron uint4
// loads, JW=10 consecutive neurons per warp, fp32 accumulation.
__global__ __launch_bounds__(256)
void k_layer3_reduce(const int* __restrict__ ia, const int* __restrict__ ib) {
    int k    = blockIdx.x;            // 0..9
    int s    = blockIdx.y;            // 0..NS-1
    int w    = threadIdx.x >> 5;      // 0..7
    int lane = threadIdx.x & 31;

    const __half* src = g_bufB;       // layer-2 output
    unsigned long long pol = mk_policy();
    int n0 = k * GROUP + s * JS + w * JW;

    float acc[8] = {0.f,0.f,0.f,0.f,0.f,0.f,0.f,0.f};

    #pragma unroll 2
    for (int j = 0; j < JW; j++) {
        int n = n0 + j;
        int A = __ldg(ia + n);
        int B = __ldg(ib + n);
        float4 c = __ldg(&g_coef[2 * WIDTH + n]);
        uint4 av = ldg_el((const uint4*)(src + (size_t)A * BATCH) + lane, pol);
        uint4 bv = ldg_el((const uint4*)(src + (size_t)B * BATCH) + lane, pol);
        #pragma unroll
        for (int h = 0; h < 4; h++) {
            float2 a = __half22float2(((__half2*)&av)[h]);
            float2 b = __half22float2(((__half2*)&bv)[h]);
            acc[2*h]   += fmaf(c.w * a.x, b.x, fmaf(c.y, a.x, fmaf(c.z, b.x, c.x)));
            acc[2*h+1] += fmaf(c.w * a.y, b.y, fmaf(c.y, a.y, fmaf(c.z, b.y, c.x)));
        }
    }

    __shared__ float part[L3WARPS][BATCH];
    #pragma unroll
    for (int i = 0; i < 8; i++) part[w][lane * 8 + i] = acc[i];
    __syncthreads();

    // 256 threads: one batch column each, sum the 8 warp partials
    int col = threadIdx.x;
    float v = 0.f;
    #pragma unroll
    for (int i = 0; i < L3WARPS; i++) v += part[i][col];
    g_part[(size_t)(k * NS + s) * BATCH + col] = v;
}

// Stage-2: sum NS partials, scale by 1/TAU, write out[b][k]
__global__ void k_freduce(float* __restrict__ out) {
    int k = blockIdx.x;   // 0..9
    int b = threadIdx.x;  // 0..255
    float acc = 0.f;
    #pragma unroll
    for (int s = 0; s < NS; s++)
        acc += g_part[(size_t)(k * NS + s) * BATCH + b];
    out[b * KOUT + k] = acc * (1.0f / 30.0f);
}

// ---------------------------------------------------------------------------
extern "C" void kernel_launch(void* const* d_in, const int* in_sizes, int n_in,
                              void* d_out, int out_size) {
    const float* x   = (const float*)d_in[0];
    const float* w1  = (const float*)d_in[1];
    const float* w2  = (const float*)d_in[2];
    const float* w3  = (const float*)d_in[3];
    const int*   ia1 = (const int*)d_in[4];
    const int*   ib1 = (const int*)d_in[5];
    const int*   ia2 = (const int*)d_in[6];
    const int*   ib2 = (const int*)d_in[7];
    const int*   ia3 = (const int*)d_in[8];
    const int*   ib3 = (const int*)d_in[9];
    float* out = (float*)d_out;

    k_pre<<<256 + (3 * WIDTH + 255) / 256, 256>>>(x, w1, w2, w3);

    dim3 lb(32, 8);
    k_layer<<<WIDTH / 16, lb>>>(0, 1, 0,     ia1, ib1);  // xT   -> bufA
    k_layer<<<WIDTH / 16, lb>>>(1, 2, WIDTH, ia2, ib2);  // bufA -> bufB

    k_layer3_reduce<<<dim3(KOUT, NS), 256>>>(ia3, ib3);  // bufB -> partials
    k_freduce<<<KOUT, BATCH>>>(out);
}